// round 4
// baseline (speedup 1.0000x reference)
#include <cuda_runtime.h>
#include <cuda_bf16.h>
#include <cstdint>

// ---------------- problem constants ----------------
#define BB   8
#define NN   2048
#define DIN  2
#define DS   32
#define DO   32
#define GE   8
#define HID  32
#define DCAT 66
#define DGI  74
#define DBASIS 396
#define GOUT 96

#define TOTN (BB*NN)
#define SZ66 ((size_t)TOTN*DCAT)
#define SZ32 ((size_t)TOTN*DO)

__device__ float g_scratch[6*1081344 + 2*524288];

#define OFF_X  ((size_t)0)
#define OFF_C  (SZ66)
#define OFF_T0 (2*SZ66)
#define OFF_T1 (3*SZ66)
#define OFF_T2 (4*SZ66)
#define OFF_T3 (5*SZ66)
#define OFF_ST (6*SZ66)
#define OFF_R  (6*SZ66 + SZ32)

__device__ __forceinline__ float sigmoidf_(float x) {
    return 1.0f / (1.0f + __expf(-x));
}

// ---------------------------------------------------------------------------
// mma / ldmatrix helpers
// ---------------------------------------------------------------------------
__device__ __forceinline__ void ldsm4(uint32_t r[4], const void* p) {
    uint32_t a = (uint32_t)__cvta_generic_to_shared(p);
    asm volatile("ldmatrix.sync.aligned.m8n8.x4.shared.b16 {%0,%1,%2,%3},[%4];"
        : "=r"(r[0]), "=r"(r[1]), "=r"(r[2]), "=r"(r[3]) : "r"(a));
}
__device__ __forceinline__ void ldsm4t(uint32_t& r0, uint32_t& r1, uint32_t& r2, uint32_t& r3,
                                       const void* p) {
    uint32_t a = (uint32_t)__cvta_generic_to_shared(p);
    asm volatile("ldmatrix.sync.aligned.m8n8.x4.trans.shared.b16 {%0,%1,%2,%3},[%4];"
        : "=r"(r0), "=r"(r1), "=r"(r2), "=r"(r3) : "r"(a));
}
__device__ __forceinline__ void ldsm2t(uint32_t r[2], const void* p) {
    uint32_t a = (uint32_t)__cvta_generic_to_shared(p);
    asm volatile("ldmatrix.sync.aligned.m8n8.x2.trans.shared.b16 {%0,%1},[%2];"
        : "=r"(r[0]), "=r"(r[1]) : "r"(a));
}
__device__ __forceinline__ void mma_bf16(float c[4], const uint32_t a[4], const uint32_t b[2]) {
    asm volatile(
        "mma.sync.aligned.m16n8k16.row.col.f32.bf16.bf16.f32 "
        "{%0,%1,%2,%3},{%4,%5,%6,%7},{%8,%9},{%0,%1,%2,%3};"
        : "+f"(c[0]), "+f"(c[1]), "+f"(c[2]), "+f"(c[3])
        : "r"(a[0]), "r"(a[1]), "r"(a[2]), "r"(a[3]), "r"(b[0]), "r"(b[1]));
}

// ---------------------------------------------------------------------------
// Kernel 1: prep
// ---------------------------------------------------------------------------
__global__ void prep_kernel(const float* __restrict__ xt,
                            const float* __restrict__ s1,
                            const float* __restrict__ s2,
                            const float* __restrict__ ge,
                            const float* __restrict__ mlp_w,
                            const float* __restrict__ mlp_b,
                            float* __restrict__ gX,
                            float* __restrict__ gstate)
{
    __shared__ float sg[8][DGI];
    const int t  = threadIdx.x;
    const int nb = blockIdx.x * 8;

    for (int idx = t; idx < 8 * DGI; idx += 256) {
        int nn = idx / DGI, i = idx % DGI;
        int node = nb + nn;
        float v;
        if (i < DIN)            v = xt[node*DIN + i];
        else if (i < DIN+DS)    v = s1[node*DS + (i-DIN)];
        else if (i < DIN+2*DS)  v = s2[node*DS + (i-DIN-DS)];
        else                    v = ge[node*GE + (i-DIN-2*DS)];
        sg[nn][i] = v;
    }
    __syncthreads();

    for (int idx = t; idx < 8 * DCAT; idx += 256) {
        int nn = idx / DCAT, i = idx % DCAT;
        gX[(size_t)(nb+nn)*DCAT + i] = sg[nn][i];
    }

    const int n = t >> 5;
    const int c = t & 31;
    float acc = mlp_b[c];
#pragma unroll 8
    for (int i = 0; i < DGI; i++)
        acc = fmaf(sg[n][i], mlp_w[i*DO + c], acc);
    float mr = sigmoidf_(acc);

    int node = nb + n;
    float a = s1[node*DS + c];
    float b = s2[node*DS + c];
    gstate[node*DS + c] = mr*a + (1.0f - mr)*b;
}

// ---------------------------------------------------------------------------
// Kernel 2: tensor-core GEMM, M=128 tile, 4 warps (64 rows x 40 cols each)
// dynamic smem, double-buffered.
// ---------------------------------------------------------------------------
#define GM 128
#define AELEM 5120     // 128*40 per buffer
#define BELEM 2816     // 32*88 per buffer
#define SMEM_BYTES ((4*AELEM + 4*BELEM)*2)

__global__ __launch_bounds__(128) void gemm_tc(const float* __restrict__ A,
                                               const float* __restrict__ Xin,
                                               const float* __restrict__ Base,
                                               float* __restrict__ Out,
                                               float alpha, float beta)
{
    extern __shared__ __nv_bfloat16 dsm[];
    __nv_bfloat16* pAh = dsm;                       // [2][128][40]
    __nv_bfloat16* pAl = dsm + 2*AELEM;
    __nv_bfloat16* pBh = dsm + 4*AELEM;             // [2][32][88]
    __nv_bfloat16* pBl = dsm + 4*AELEM + 2*BELEM;

    const int t    = threadIdx.x;
    const int b    = blockIdx.y;
    const int row0 = blockIdx.x * GM;

    const float* Ab = A + ((size_t)b * NN + row0) * NN;
    const float* Xb = Xin + (size_t)b * NN * DCAT;

    // zero B pad cols (66..87) in both buffers once
    for (int idx = t; idx < 2*32*22; idx += 128) {
        int bb = idx / (32*22);
        int rem = idx - bb*(32*22);
        int kk = rem / 22, cc = 66 + rem % 22;
        pBh[bb*BELEM + kk*88 + cc] = __float2bfloat16(0.0f);
        pBl[bb*BELEM + kk*88 + cc] = __float2bfloat16(0.0f);
    }

    const int lane = t & 31;
    const int wid  = t >> 5;
    const int wm   = wid >> 1;          // 0..1 : 64-row half
    const int wn   = wid & 1;           // 0..1 : 40-col half

    const int l_r = (lane & 7) + ((lane >> 3) & 1) * 8;
    const int l_c = (lane >> 4) * 8;

    float acc[4][5][4];
#pragma unroll
    for (int mi = 0; mi < 4; mi++)
#pragma unroll
        for (int j = 0; j < 5; j++)
#pragma unroll
            for (int q = 0; q < 4; q++) acc[mi][j][q] = 0.0f;

    float4 areg[8];
    float2 xreg[9];
    const int ar = t;                   // A row 0..127, whole 32-k row

    auto LOADR = [&](int k0) {
#pragma unroll
        for (int i = 0; i < 8; i++)
            areg[i] = *(const float4*)(Ab + (size_t)ar*NN + k0 + 4*i);
#pragma unroll
        for (int i = 0; i < 9; i++) {
            int idx = t + 128*i;
            if (idx < 1056) {
                int k = idx / 33, p = idx - 33*k;
                xreg[i] = *(const float2*)(Xb + (size_t)(k0 + k)*DCAT + 2*p);
            }
        }
    };
    auto STORE = [&](int buf) {
        __nv_bfloat16* ah = pAh + buf*AELEM + ar*40;
        __nv_bfloat16* al = pAl + buf*AELEM + ar*40;
#pragma unroll
        for (int i = 0; i < 8; i++) {
            float4 v = areg[i];
            __nv_bfloat16 hx = __float2bfloat16(v.x);
            __nv_bfloat16 hy = __float2bfloat16(v.y);
            __nv_bfloat16 hz = __float2bfloat16(v.z);
            __nv_bfloat16 hw = __float2bfloat16(v.w);
            *(__nv_bfloat162*)&ah[4*i]     = __halves2bfloat162(hx, hy);
            *(__nv_bfloat162*)&ah[4*i + 2] = __halves2bfloat162(hz, hw);
            __nv_bfloat16 lx = __float2bfloat16(v.x - __bfloat162float(hx));
            __nv_bfloat16 ly = __float2bfloat16(v.y - __bfloat162float(hy));
            __nv_bfloat16 lz = __float2bfloat16(v.z - __bfloat162float(hz));
            __nv_bfloat16 lw = __float2bfloat16(v.w - __bfloat162float(hw));
            *(__nv_bfloat162*)&al[4*i]     = __halves2bfloat162(lx, ly);
            *(__nv_bfloat162*)&al[4*i + 2] = __halves2bfloat162(lz, lw);
        }
#pragma unroll
        for (int i = 0; i < 9; i++) {
            int idx = t + 128*i;
            if (idx < 1056) {
                int k = idx / 33, p = idx - 33*k;
                float2 v = xreg[i];
                __nv_bfloat16 hx = __float2bfloat16(v.x);
                __nv_bfloat16 hy = __float2bfloat16(v.y);
                *(__nv_bfloat162*)&pBh[buf*BELEM + k*88 + 2*p] = __halves2bfloat162(hx, hy);
                __nv_bfloat16 lx = __float2bfloat16(v.x - __bfloat162float(hx));
                __nv_bfloat16 ly = __float2bfloat16(v.y - __bfloat162float(hy));
                *(__nv_bfloat162*)&pBl[buf*BELEM + k*88 + 2*p] = __halves2bfloat162(lx, ly);
            }
        }
    };
    auto MMA = [&](int buf) {
#pragma unroll
        for (int kk = 0; kk < 32; kk += 16) {
            uint32_t ah[4][4], al[4][4];
#pragma unroll
            for (int mi = 0; mi < 4; mi++) {
                const int r = wm*64 + mi*16 + l_r;
                ldsm4(ah[mi], pAh + buf*AELEM + r*40 + kk + l_c);
                ldsm4(al[mi], pAl + buf*AELEM + r*40 + kk + l_c);
            }
            uint32_t bh[5][2], bl[5][2];
            const __nv_bfloat16* bhp = pBh + buf*BELEM + (kk + l_r)*88;
            const __nv_bfloat16* blp = pBl + buf*BELEM + (kk + l_r)*88;
            ldsm4t(bh[0][0], bh[0][1], bh[1][0], bh[1][1], bhp + wn*40 + 0  + l_c);
            ldsm4t(bh[2][0], bh[2][1], bh[3][0], bh[3][1], bhp + wn*40 + 16 + l_c);
            ldsm2t(bh[4], pBh + buf*BELEM + (kk + l_r)*88 + wn*40 + 32);
            ldsm4t(bl[0][0], bl[0][1], bl[1][0], bl[1][1], blp + wn*40 + 0  + l_c);
            ldsm4t(bl[2][0], bl[2][1], bl[3][0], bl[3][1], blp + wn*40 + 16 + l_c);
            ldsm2t(bl[4], pBl + buf*BELEM + (kk + l_r)*88 + wn*40 + 32);
#pragma unroll
            for (int mi = 0; mi < 4; mi++)
#pragma unroll
                for (int j = 0; j < 5; j++) {
                    mma_bf16(acc[mi][j], ah[mi], bh[j]);
                    mma_bf16(acc[mi][j], al[mi], bh[j]);
                    mma_bf16(acc[mi][j], ah[mi], bl[j]);
                }
        }
    };

    LOADR(0);
    STORE(0);
    __syncthreads();

    for (int c = 0; c < NN/32; c++) {
        int buf = c & 1;
        if (c < NN/32 - 1) LOADR((c + 1) * 32);
        MMA(buf);
        if (c < NN/32 - 1) STORE(buf ^ 1);
        __syncthreads();
    }

    const int ro = lane >> 2;
    const int co = (lane & 3) * 2;
#pragma unroll
    for (int mi = 0; mi < 4; mi++) {
#pragma unroll
        for (int j = 0; j < 5; j++) {
            int col = wn*40 + j*8 + co;
            if (col < DCAT) {
#pragma unroll
                for (int h = 0; h < 2; h++) {
                    int row = row0 + wm*64 + mi*16 + ro + h*8;
                    size_t o = ((size_t)b * NN + row) * DCAT + col;
                    float2 v;
                    v.x = alpha * acc[mi][j][h*2 + 0];
                    v.y = alpha * acc[mi][j][h*2 + 1];
                    if (Base) {
                        float2 bs = *(const float2*)(Base + o);
                        v.x = fmaf(beta, bs.x, v.x);
                        v.y = fmaf(beta, bs.y, v.y);
                    }
                    *(float2*)(Out + o) = v;
                }
            }
        }
    }
}

// ---------------------------------------------------------------------------
// Kernel 3: gate combine — 16 nodes/block, 384 thr (4 groups x 96ch, 4 nodes)
// ---------------------------------------------------------------------------
__global__ __launch_bounds__(384) void combine_gate(
                             const float* __restrict__ X,
                             const float* __restrict__ T0,
                             const float* __restrict__ T1,
                             const float* __restrict__ T2,
                             const float* __restrict__ T3,
                             const float* __restrict__ gate_w,
                             const float* __restrict__ gate_b,
                             const float* __restrict__ xt,
                             const float* __restrict__ s1,
                             const float* __restrict__ s2,
                             float* __restrict__ cand,
                             float* __restrict__ r_out)
{
    __shared__ float s[16][DBASIS];
    const int t  = threadIdx.x;
    const int nb = blockIdx.x * 16;

    for (int idx = t; idx < 16*DBASIS; idx += 384) {
        int n = idx / DBASIS, i = idx - n*DBASIS;
        int term = i / DCAT, w = i - term*DCAT;
        const float* src;
        switch (term) {
            case 0: src = X;  break;
            case 1: src = T0; break;
            case 2: src = T1; break;
            case 3: src = X;  break;
            case 4: src = T2; break;
            default: src = T3; break;
        }
        s[n][i] = src[(size_t)(nb+n)*DCAT + w];
    }
    __syncthreads();

    const int c = t % 96;
    const int g = t / 96;           // 0..3, nodes g*4..g*4+3
    float acc[4];
    float bc = gate_b[c];
#pragma unroll
    for (int q = 0; q < 4; q++) acc[q] = bc;

    for (int i = 0; i < DBASIS; i++) {
        float w = __ldg(&gate_w[i*GOUT + c]);
#pragma unroll
        for (int q = 0; q < 4; q++)
            acc[q] = fmaf(s[g*4 + q][i], w, acc[q]);
    }

#pragma unroll
    for (int q = 0; q < 4; q++) {
        int node = nb + g*4 + q;
        float v = sigmoidf_(acc[q]);
        if (c < DO) {
            cand[(size_t)node*DCAT + DIN + c] = v * s1[node*DS + c];
        } else if (c < 2*DO) {
            int cc = c - DO;
            cand[(size_t)node*DCAT + DIN + DS + cc] = v * s2[node*DS + cc];
        } else {
            r_out[node*DO + (c - 2*DO)] = v;
        }
        if (c < DIN)
            cand[(size_t)node*DCAT + c] = xt[node*DIN + c];
    }
}

// ---------------------------------------------------------------------------
// Kernel 4: final — 16 nodes/block, 512 thr
// ---------------------------------------------------------------------------
__global__ __launch_bounds__(512) void final_kernel(
                             const float* __restrict__ C,
                             const float* __restrict__ T0,
                             const float* __restrict__ T1,
                             const float* __restrict__ T2,
                             const float* __restrict__ T3,
                             const float* __restrict__ upd_w,
                             const float* __restrict__ upd_b,
                             const float* __restrict__ hop_w,
                             const float* __restrict__ hop_b,
                             const float* __restrict__ g_r,
                             const float* __restrict__ g_state,
                             float* __restrict__ out)
{
    __shared__ float s[16][DBASIS];
    __shared__ float hsh[16][DO];
    const int t  = threadIdx.x;
    const int nb = blockIdx.x * 16;

    for (int idx = t; idx < 16*DBASIS; idx += 512) {
        int n = idx / DBASIS, i = idx - n*DBASIS;
        int term = i / DCAT, w = i - term*DCAT;
        const float* src;
        switch (term) {
            case 0: src = C;  break;
            case 1: src = T0; break;
            case 2: src = T1; break;
            case 3: src = C;  break;
            case 4: src = T2; break;
            default: src = T3; break;
        }
        s[n][i] = src[(size_t)(nb+n)*DCAT + w];
    }
    __syncthreads();

    const int n = t >> 5;
    const int c = t & 31;
    const int node = nb + n;

    float acc = upd_b[c];
    for (int i = 0; i < DBASIS; i++)
        acc = fmaf(s[n][i], __ldg(&upd_w[i*DO + c]), acc);

    float hc = tanhf(acc);
    float r  = g_r[node*DO + c];
    float st = g_state[node*DS + c];
    float h  = r*st + (1.0f - r)*hc;

    out[(size_t)node*DO + c] = h;
    hsh[n][c] = h;
    __syncthreads();

    float a2 = hop_b[c];
#pragma unroll
    for (int i = 0; i < HID; i++)
        a2 = fmaf(hsh[n][i], hop_w[i*HID + c], a2);
    out[(size_t)TOTN*DO + (size_t)node*HID + c] = a2;
}

// ---------------------------------------------------------------------------
// launch
// ---------------------------------------------------------------------------
extern "C" void kernel_launch(void* const* d_in, const int* in_sizes, int n_in,
                              void* d_out, int out_size)
{
    const float* xt     = (const float*)d_in[0];
    const float* s1     = (const float*)d_in[1];
    const float* s2     = (const float*)d_in[2];
    const float* ge     = (const float*)d_in[3];
    const float* sup    = (const float*)d_in[4];
    const float* mlp_w  = (const float*)d_in[5];
    const float* mlp_b  = (const float*)d_in[6];
    const float* gate_w = (const float*)d_in[7];
    const float* gate_b = (const float*)d_in[8];
    const float* upd_w  = (const float*)d_in[9];
    const float* upd_b  = (const float*)d_in[10];
    const float* hop_w  = (const float*)d_in[11];
    const float* hop_b  = (const float*)d_in[12];
    float* out = (float*)d_out;

    float* scr = nullptr;
    cudaGetSymbolAddress((void**)&scr, g_scratch);

    float* gX  = scr + OFF_X;
    float* gC  = scr + OFF_C;
    float* gT0 = scr + OFF_T0;
    float* gT1 = scr + OFF_T1;
    float* gT2 = scr + OFF_T2;
    float* gT3 = scr + OFF_T3;
    float* gST = scr + OFF_ST;
    float* gR  = scr + OFF_R;

    const float* A0 = sup;
    const float* A1 = sup + (size_t)BB * NN * NN;

    cudaFuncSetAttribute(gemm_tc, cudaFuncAttributeMaxDynamicSharedMemorySize, SMEM_BYTES);

    dim3 ggrid(NN / GM, BB);

    prep_kernel<<<TOTN/8, 256>>>(xt, s1, s2, ge, mlp_w, mlp_b, gX, gST);

    gemm_tc<<<ggrid, 128, SMEM_BYTES>>>(A0, gX,  nullptr, gT0, 1.0f,  0.0f);
    gemm_tc<<<ggrid, 128, SMEM_BYTES>>>(A0, gT0, gX,      gT1, 2.0f, -1.0f);
    gemm_tc<<<ggrid, 128, SMEM_BYTES>>>(A1, gX,  nullptr, gT2, 1.0f,  0.0f);
    gemm_tc<<<ggrid, 128, SMEM_BYTES>>>(A1, gT2, gX,      gT3, 2.0f, -1.0f);

    combine_gate<<<TOTN/16, 384>>>(gX, gT0, gT1, gT2, gT3,
                                   gate_w, gate_b, xt, s1, s2, gC, gR);

    gemm_tc<<<ggrid, 128, SMEM_BYTES>>>(A0, gC,  nullptr, gT0, 1.0f,  0.0f);
    gemm_tc<<<ggrid, 128, SMEM_BYTES>>>(A0, gT0, gC,      gT1, 2.0f, -1.0f);
    gemm_tc<<<ggrid, 128, SMEM_BYTES>>>(A1, gC,  nullptr, gT2, 1.0f,  0.0f);
    gemm_tc<<<ggrid, 128, SMEM_BYTES>>>(A1, gT2, gC,      gT3, 2.0f, -1.0f);

    final_kernel<<<TOTN/16, 512>>>(gC, gT0, gT1, gT2, gT3,
                                   upd_w, upd_b, hop_w, hop_b,
                                   gR, gST, out);
}